// round 1
// baseline (speedup 1.0000x reference)
#include <cuda_runtime.h>

#define NN 100000
#define NE 1600000

// Scratch (static device arrays; allocation-free per harness rules).
__device__ float g_S[(size_t)NN * 128];  // "support" = h @ W
__device__ float g_A[(size_t)NN * 128];  // aggregation (init with bias, scatter-add)

// ---------------------------------------------------------------------------
// Fill a [M, D] buffer with a broadcast bias row (D is a power of two).
// ---------------------------------------------------------------------------
__global__ void fill_bias_kernel(float* __restrict__ out, const float* __restrict__ b,
                                 int total, int dmask) {
    int i = blockIdx.x * blockDim.x + threadIdx.x;
    if (i < total) out[i] = __ldg(&b[i & dmask]);
}

// ---------------------------------------------------------------------------
// Register-tiled SGEMM: C[M,N] = op(A)[M,K] @ B[K,N]
// op(A) = relu(A) when RELU_A (bias already folded into A by fill_bias).
// TM=TN=8 balances smem crossbar bytes vs FMA pipe on sm_103a.
// ---------------------------------------------------------------------------
template <int BM, int BN, int BK, int TM, int TN, bool RELU_A>
__global__ void sgemm_kernel(const float* __restrict__ A, const float* __restrict__ B,
                             float* __restrict__ C, int M, int N, int K) {
    constexpr int THREADS = (BM / TM) * (BN / TN);
    constexpr int TX = BN / TN;
    constexpr int A_F4 = BM * BK / 4;
    constexpr int A_PER = A_F4 / THREADS;
    constexpr int B_F4 = BK * BN / 4;
    constexpr int B_PER = B_F4 / THREADS;
    static_assert(A_PER * THREADS == A_F4, "A tile divisibility");
    static_assert(B_PER * THREADS == B_F4, "B tile divisibility");

    __shared__ float As[BK][BM + 4];   // transposed, padded (16B-aligned rows)
    __shared__ float Bs[BK][BN];

    const int tid = threadIdx.x;
    const int bm = blockIdx.y * BM;
    const int bn = blockIdx.x * BN;
    const int tx = tid % TX;
    const int ty = tid / TX;

    float acc[TM][TN];
#pragma unroll
    for (int m = 0; m < TM; m++)
#pragma unroll
        for (int n = 0; n < TN; n++) acc[m][n] = 0.0f;

    for (int kt = 0; kt < K; kt += BK) {
        // Load A tile (BM x BK) as float4, store transposed into As.
#pragma unroll
        for (int i = 0; i < A_PER; i++) {
            int f4 = tid + i * THREADS;
            int row = f4 / (BK / 4);
            int c4 = f4 % (BK / 4);
            float4 v = make_float4(0.f, 0.f, 0.f, 0.f);
            int grow = bm + row;
            if (grow < M)
                v = *(const float4*)&A[(size_t)grow * K + kt + c4 * 4];
            if (RELU_A) {
                v.x = fmaxf(v.x, 0.f); v.y = fmaxf(v.y, 0.f);
                v.z = fmaxf(v.z, 0.f); v.w = fmaxf(v.w, 0.f);
            }
            As[c4 * 4 + 0][row] = v.x;
            As[c4 * 4 + 1][row] = v.y;
            As[c4 * 4 + 2][row] = v.z;
            As[c4 * 4 + 3][row] = v.w;
        }
        // Load B tile (BK x BN) row-major.
#pragma unroll
        for (int i = 0; i < B_PER; i++) {
            int f4 = tid + i * THREADS;
            int row = f4 / (BN / 4);
            int c4 = f4 % (BN / 4);
            *(float4*)&Bs[row][c4 * 4] =
                *(const float4*)&B[(size_t)(kt + row) * N + bn + c4 * 4];
        }
        __syncthreads();

#pragma unroll
        for (int k = 0; k < BK; k++) {
            float a[TM], bb[TN];
#pragma unroll
            for (int m = 0; m < TM; m += 4) {
                float4 v = *(const float4*)&As[k][ty * TM + m];
                a[m] = v.x; a[m + 1] = v.y; a[m + 2] = v.z; a[m + 3] = v.w;
            }
#pragma unroll
            for (int n = 0; n < TN; n += 4) {
                float4 v = *(const float4*)&Bs[k][tx * TN + n];
                bb[n] = v.x; bb[n + 1] = v.y; bb[n + 2] = v.z; bb[n + 3] = v.w;
            }
#pragma unroll
            for (int m = 0; m < TM; m++)
#pragma unroll
                for (int n = 0; n < TN; n++) acc[m][n] = fmaf(a[m], bb[n], acc[m][n]);
        }
        __syncthreads();
    }

    // Store
#pragma unroll
    for (int m = 0; m < TM; m++) {
        int row = bm + ty * TM + m;
        if (row < M) {
#pragma unroll
            for (int n = 0; n < TN; n += 4) {
                float4 v = make_float4(acc[m][n], acc[m][n + 1], acc[m][n + 2], acc[m][n + 3]);
                *(float4*)&C[(size_t)row * N + bn + tx * TN + n] = v;
            }
        }
    }
}

// ---------------------------------------------------------------------------
// Edge-parallel SpMM scatter: A[dst] += w * S[src], vector (16B) global RED.
// D=128: one warp == one edge (uniform src/dst/w loads, coalesced 512B gather).
// ---------------------------------------------------------------------------
template <int D>
__global__ void spmm_kernel(const float* __restrict__ S, const int* __restrict__ src,
                            const int* __restrict__ dst, const float* __restrict__ w,
                            float* __restrict__ A, int E) {
    constexpr int CPE = D / 4;  // float4 chunks per edge
    long long t = (long long)blockIdx.x * blockDim.x + threadIdx.x;
    int e = (int)(t / CPE);
    int c = (int)(t % CPE);
    if (e >= E) return;
    int s = __ldg(&src[e]);
    int d = __ldg(&dst[e]);
    float wt = __ldg(&w[e]);
    float4 v = *((const float4*)(S + (size_t)s * D) + c);
    v.x *= wt; v.y *= wt; v.z *= wt; v.w *= wt;
    float* ap = A + (size_t)d * D + c * 4;
    asm volatile("red.global.add.v4.f32 [%0], {%1, %2, %3, %4};"
                 :: "l"(ap), "f"(v.x), "f"(v.y), "f"(v.z), "f"(v.w)
                 : "memory");
}

// ---------------------------------------------------------------------------
extern "C" void kernel_launch(void* const* d_in, const int* in_sizes, int n_in,
                              void* d_out, int out_size) {
    const float* x    = (const float*)d_in[0];
    const int*   esrc = (const int*)d_in[1];
    const int*   edst = (const int*)d_in[2];
    const float* ew   = (const float*)d_in[3];
    const float* W1   = (const float*)d_in[4];
    const float* b1   = (const float*)d_in[5];
    const float* W2   = (const float*)d_in[6];
    const float* b2   = (const float*)d_in[7];
    const float* W3   = (const float*)d_in[8];
    const float* b3   = (const float*)d_in[9];
    float* out = (float*)d_out;

    float *S, *A;
    cudaGetSymbolAddress((void**)&S, g_S);
    cudaGetSymbolAddress((void**)&A, g_A);

    const int M = NN, E = NE;
    const int gy = (M + 127) / 128;

    // ----- Layer 1: support = x @ W1 (K=256, N=128) -----
    sgemm_kernel<128, 128, 8, 8, 8, false>
        <<<dim3(1, gy), 256>>>(x, W1, S, M, 128, 256);
    fill_bias_kernel<<<(M * 128 + 255) / 256, 256>>>(A, b1, M * 128, 127);
    spmm_kernel<128><<<(int)(((long long)E * 32 + 255) / 256), 256>>>(S, esrc, edst, ew, A, E);

    // ----- Layer 2: support = relu(A) @ W2 (K=128, N=64) -----
    sgemm_kernel<128, 64, 8, 8, 8, true>
        <<<dim3(1, gy), 128>>>(A, W2, S, M, 64, 128);
    fill_bias_kernel<<<(M * 64 + 255) / 256, 256>>>(A, b2, M * 64, 63);
    spmm_kernel<64><<<(int)(((long long)E * 16 + 255) / 256), 256>>>(S, esrc, edst, ew, A, E);

    // ----- Layer 3: support = relu(A) @ W3 (K=64, N=64), scatter into d_out -----
    sgemm_kernel<128, 64, 8, 8, 8, true>
        <<<dim3(1, gy), 128>>>(A, W3, S, M, 64, 64);
    fill_bias_kernel<<<(M * 64 + 255) / 256, 256>>>(out, b3, M * 64, 63);
    spmm_kernel<64><<<(int)(((long long)E * 16 + 255) / 256), 256>>>(S, esrc, edst, ew, out, E);
}

// round 2
// speedup vs baseline: 1.4571x; 1.4571x over previous
#include <cuda_runtime.h>

#define NN 100000
#define NE 1600000
#define NBLK_SCAN 98   // ceil(100000/1024)

// Scratch (static device arrays; allocation-free per harness rules).
__device__ float g_S[(size_t)NN * 128];   // "support" = h @ W
__device__ float g_A[(size_t)NN * 128];   // aggregated activations
__device__ int   g_cnt[NN];               // per-dst degree
__device__ int   g_pre[NN];               // block-local exclusive scan
__device__ int   g_bsum[1024];            // per-block sums (padded)
__device__ int   g_btop[1024];            // scanned block sums
__device__ int   g_rowptr[NN + 1];        // CSR row pointers (by dst)
__device__ int   g_cursor[NN];            // scatter cursors
__device__ int2  g_csr[NE];               // packed (src, weight_bits) per edge

// ---------------------------------------------------------------------------
// CSR build: zero -> count -> scan (2-level) -> offsets -> scatter
// ---------------------------------------------------------------------------
__global__ void zero_kernel(int* __restrict__ p, int n) {
    int i = blockIdx.x * blockDim.x + threadIdx.x;
    if (i < n) p[i] = 0;
}

__global__ void count_kernel(const int* __restrict__ dst, int* __restrict__ cnt, int E) {
    int e = blockIdx.x * blockDim.x + threadIdx.x;
    if (e < E) atomicAdd(&cnt[__ldg(&dst[e])], 1);
}

// Block-level exclusive scan (1024/block, Hillis-Steele, ping-pong buffers).
__global__ void scan_block_kernel(const int* __restrict__ in, int* __restrict__ outx,
                                  int* __restrict__ sums, int n) {
    __shared__ int s[2][1024];
    int tid = threadIdx.x;
    int i = blockIdx.x * 1024 + tid;
    int v = (i < n) ? in[i] : 0;
    int pin = 0;
    s[0][tid] = v;
    __syncthreads();
#pragma unroll
    for (int off = 1; off < 1024; off <<= 1) {
        int t = s[pin][tid] + ((tid >= off) ? s[pin][tid - off] : 0);
        s[pin ^ 1][tid] = t;
        pin ^= 1;
        __syncthreads();
    }
    if (i < n) outx[i] = s[pin][tid] - v;   // exclusive
    if (sums != nullptr && tid == 1023) sums[blockIdx.x] = s[pin][1023];
}

__global__ void add_offsets_kernel(const int* __restrict__ pre, const int* __restrict__ top,
                                   int* __restrict__ rowptr, int* __restrict__ cursor, int n) {
    int i = blockIdx.x * blockDim.x + threadIdx.x;
    if (i < n) {
        int v = pre[i] + __ldg(&top[i >> 10]);
        rowptr[i] = v;
        cursor[i] = v;
    }
    if (i == 0) rowptr[n] = NE;
}

__global__ void scatter_kernel(const int* __restrict__ src, const int* __restrict__ dst,
                               const float* __restrict__ w, int* __restrict__ cursor,
                               int2* __restrict__ csr, int E) {
    int e = blockIdx.x * blockDim.x + threadIdx.x;
    if (e >= E) return;
    int d = __ldg(&dst[e]);
    int pos = atomicAdd(&cursor[d], 1);
    csr[pos] = make_int2(__ldg(&src[e]), __float_as_int(__ldg(&w[e])));
}

// ---------------------------------------------------------------------------
// Register-tiled SGEMM with double-buffered smem + register prefetch.
// C[M,N] = A[M,K] @ B[K,N]
// ---------------------------------------------------------------------------
template <int BM, int BN, int BK, int TM, int TN>
__global__ void sgemm_db_kernel(const float* __restrict__ A, const float* __restrict__ B,
                                float* __restrict__ C, int M, int N, int K) {
    constexpr int THREADS = (BM / TM) * (BN / TN);
    constexpr int TX = BN / TN;
    constexpr int A_F4 = BM * BK / 4;
    constexpr int A_PER = A_F4 / THREADS;
    constexpr int B_F4 = BK * BN / 4;
    constexpr int B_PER = B_F4 / THREADS;
    static_assert(A_PER * THREADS == A_F4, "A tile divisibility");
    static_assert(B_PER * THREADS == B_F4, "B tile divisibility");

    __shared__ float As[2][BK][BM + 4];
    __shared__ float Bs[2][BK][BN];

    const int tid = threadIdx.x;
    const int bm = blockIdx.y * BM;
    const int bn = blockIdx.x * BN;
    const int tx = tid % TX;
    const int ty = tid / TX;

    float4 pa[A_PER], pb[B_PER];

    auto loadA = [&](int kt) {
#pragma unroll
        for (int i = 0; i < A_PER; i++) {
            int f4 = tid + i * THREADS;
            int row = f4 / (BK / 4);
            int grow = bm + row;
            float4 v = make_float4(0.f, 0.f, 0.f, 0.f);
            if (grow < M)
                v = *(const float4*)&A[(size_t)grow * K + kt + (f4 % (BK / 4)) * 4];
            pa[i] = v;
        }
    };
    auto loadB = [&](int kt) {
#pragma unroll
        for (int i = 0; i < B_PER; i++) {
            int f4 = tid + i * THREADS;
            int row = f4 / (BN / 4);
            pb[i] = *(const float4*)&B[(size_t)(kt + row) * N + bn + (f4 % (BN / 4)) * 4];
        }
    };
    auto storeT = [&](int buf) {
#pragma unroll
        for (int i = 0; i < A_PER; i++) {
            int f4 = tid + i * THREADS;
            int row = f4 / (BK / 4);
            int c = (f4 % (BK / 4)) * 4;
            As[buf][c + 0][row] = pa[i].x;
            As[buf][c + 1][row] = pa[i].y;
            As[buf][c + 2][row] = pa[i].z;
            As[buf][c + 3][row] = pa[i].w;
        }
#pragma unroll
        for (int i = 0; i < B_PER; i++) {
            int f4 = tid + i * THREADS;
            int row = f4 / (BN / 4);
            *(float4*)&Bs[buf][row][(f4 % (BN / 4)) * 4] = pb[i];
        }
    };

    float acc[TM][TN];
#pragma unroll
    for (int m = 0; m < TM; m++)
#pragma unroll
        for (int n = 0; n < TN; n++) acc[m][n] = 0.0f;

    loadA(0);
    loadB(0);
    storeT(0);
    __syncthreads();

    int buf = 0;
    for (int kt = 0; kt < K; kt += BK) {
        bool more = (kt + BK) < K;
        if (more) { loadA(kt + BK); loadB(kt + BK); }

#pragma unroll
        for (int k = 0; k < BK; k++) {
            float a[TM], bb[TN];
#pragma unroll
            for (int m = 0; m < TM; m += 4) {
                float4 v = *(const float4*)&As[buf][k][ty * TM + m];
                a[m] = v.x; a[m + 1] = v.y; a[m + 2] = v.z; a[m + 3] = v.w;
            }
#pragma unroll
            for (int n = 0; n < TN; n += 4) {
                float4 v = *(const float4*)&Bs[buf][k][tx * TN + n];
                bb[n] = v.x; bb[n + 1] = v.y; bb[n + 2] = v.z; bb[n + 3] = v.w;
            }
#pragma unroll
            for (int m = 0; m < TM; m++)
#pragma unroll
                for (int n = 0; n < TN; n++) acc[m][n] = fmaf(a[m], bb[n], acc[m][n]);
        }

        if (more) {
            storeT(buf ^ 1);
            __syncthreads();
            buf ^= 1;
        }
    }

#pragma unroll
    for (int m = 0; m < TM; m++) {
        int row = bm + ty * TM + m;
        if (row < M) {
#pragma unroll
            for (int n = 0; n < TN; n += 4) {
                float4 v = make_float4(acc[m][n], acc[m][n + 1], acc[m][n + 2], acc[m][n + 3]);
                *(float4*)&C[(size_t)row * N + bn + tx * TN + n] = v;
            }
        }
    }
}

// ---------------------------------------------------------------------------
// CSR pull-mode SpMM: out[n] = relu?( bias + sum_{e in CSR[n]} w_e * S[src_e] )
// One warp per destination node; atomic-free; coalesced write.
// ---------------------------------------------------------------------------
template <int D, bool RELU>
__global__ void spmm_csr_kernel(const float* __restrict__ S, const int2* __restrict__ csr,
                                const int* __restrict__ rowptr, const float* __restrict__ bias,
                                float* __restrict__ out) {
    int warp = (blockIdx.x * blockDim.x + threadIdx.x) >> 5;
    int lane = threadIdx.x & 31;
    if (warp >= NN) return;
    int start = __ldg(&rowptr[warp]);
    int end   = __ldg(&rowptr[warp + 1]);

    if (D == 128) {
        float4 acc = __ldg((const float4*)bias + lane);
        for (int e = start; e < end; e++) {
            int2 rec = __ldg(&csr[e]);
            float wt = __int_as_float(rec.y);
            float4 v = __ldg((const float4*)(S + (size_t)rec.x * 128) + lane);
            acc.x = fmaf(wt, v.x, acc.x);
            acc.y = fmaf(wt, v.y, acc.y);
            acc.z = fmaf(wt, v.z, acc.z);
            acc.w = fmaf(wt, v.w, acc.w);
        }
        if (RELU) {
            acc.x = fmaxf(acc.x, 0.f); acc.y = fmaxf(acc.y, 0.f);
            acc.z = fmaxf(acc.z, 0.f); acc.w = fmaxf(acc.w, 0.f);
        }
        *((float4*)(out + (size_t)warp * 128) + lane) = acc;
    } else {
        float2 acc = __ldg((const float2*)bias + lane);
        for (int e = start; e < end; e++) {
            int2 rec = __ldg(&csr[e]);
            float wt = __int_as_float(rec.y);
            float2 v = __ldg((const float2*)(S + (size_t)rec.x * 64) + lane);
            acc.x = fmaf(wt, v.x, acc.x);
            acc.y = fmaf(wt, v.y, acc.y);
        }
        if (RELU) {
            acc.x = fmaxf(acc.x, 0.f);
            acc.y = fmaxf(acc.y, 0.f);
        }
        *((float2*)(out + (size_t)warp * 64) + lane) = acc;
    }
}

// ---------------------------------------------------------------------------
extern "C" void kernel_launch(void* const* d_in, const int* in_sizes, int n_in,
                              void* d_out, int out_size) {
    const float* x    = (const float*)d_in[0];
    const int*   esrc = (const int*)d_in[1];
    const int*   edst = (const int*)d_in[2];
    const float* ew   = (const float*)d_in[3];
    const float* W1   = (const float*)d_in[4];
    const float* b1   = (const float*)d_in[5];
    const float* W2   = (const float*)d_in[6];
    const float* b2   = (const float*)d_in[7];
    const float* W3   = (const float*)d_in[8];
    const float* b3   = (const float*)d_in[9];
    float* out = (float*)d_out;

    float *S, *A;
    int *cnt, *pre, *bsum, *btop, *rowptr, *cursor;
    int2* csr;
    cudaGetSymbolAddress((void**)&S, g_S);
    cudaGetSymbolAddress((void**)&A, g_A);
    cudaGetSymbolAddress((void**)&cnt, g_cnt);
    cudaGetSymbolAddress((void**)&pre, g_pre);
    cudaGetSymbolAddress((void**)&bsum, g_bsum);
    cudaGetSymbolAddress((void**)&btop, g_btop);
    cudaGetSymbolAddress((void**)&rowptr, g_rowptr);
    cudaGetSymbolAddress((void**)&cursor, g_cursor);
    cudaGetSymbolAddress((void**)&csr, g_csr);

    const int M = NN, E = NE;
    const int gy = (M + 127) / 128;

    // ----- Build dst-CSR (once per launch) -----
    zero_kernel<<<(NN + 511) / 512, 512>>>(cnt, NN);
    count_kernel<<<(E + 511) / 512, 512>>>(edst, cnt, E);
    scan_block_kernel<<<NBLK_SCAN, 1024>>>(cnt, pre, bsum, NN);
    scan_block_kernel<<<1, 1024>>>(bsum, btop, nullptr, NBLK_SCAN);
    add_offsets_kernel<<<(NN + 511) / 512, 512>>>(pre, btop, rowptr, cursor, NN);
    scatter_kernel<<<(E + 511) / 512, 512>>>(esrc, edst, ew, cursor, csr, E);

    // ----- Layer 1: S = x @ W1 (K=256, N=128); A = relu(adj@S + b1) -----
    sgemm_db_kernel<128, 128, 16, 8, 8>
        <<<dim3(1, gy), 256>>>(x, W1, S, M, 128, 256);
    spmm_csr_kernel<128, true><<<(NN + 7) / 8, 256>>>(S, csr, rowptr, b1, A);

    // ----- Layer 2: S = A @ W2 (K=128, N=64); A = relu(adj@S + b2) -----
    sgemm_db_kernel<128, 64, 16, 8, 8>
        <<<dim3(1, gy), 128>>>(A, W2, S, M, 64, 128);
    spmm_csr_kernel<64, true><<<(NN + 7) / 8, 256>>>(S, csr, rowptr, b2, A);

    // ----- Layer 3: S = A @ W3 (K=64, N=64); out = adj@S + b3 -----
    sgemm_db_kernel<128, 64, 16, 8, 8>
        <<<dim3(1, gy), 128>>>(A, W3, S, M, 64, 64);
    spmm_csr_kernel<64, false><<<(NN + 7) / 8, 256>>>(S, csr, rowptr, b3, out);
}

// round 4
// speedup vs baseline: 1.9967x; 1.3703x over previous
#include <cuda_runtime.h>
#include <cuda_bf16.h>
#include <cstdint>

#define NN 100000
#define NE 1600000
#define NBLK_SCAN 98   // ceil(100000/1024)

// ---------------------------------------------------------------------------
// Scratch (static device arrays; allocation-free per harness rules).
// ---------------------------------------------------------------------------
__device__ float         g_S[(size_t)NN * 128];   // "support" = h @ W (fp32)
__device__ __nv_bfloat16 g_H[(size_t)NN * 256];   // hi-plane of GEMM A operand
__device__ __nv_bfloat16 g_L[(size_t)NN * 256];   // lo-plane of GEMM A operand
__device__ __nv_bfloat16 g_WH[45056];             // weight hi planes (W1T|W2T|W3T)
__device__ __nv_bfloat16 g_WL[45056];             // weight lo planes
__device__ int   g_cnt[NN];
__device__ int   g_pre[NN];
__device__ int   g_bsum[1024];
__device__ int   g_btop[1024];
__device__ int   g_rowptr[NN + 1];
__device__ int   g_cursor[NN];
__device__ int2  g_csr[NE];

// ---------------------------------------------------------------------------
// Helpers
// ---------------------------------------------------------------------------
__device__ __forceinline__ uint32_t smem_u32(const void* p) {
    uint32_t a;
    asm("{ .reg .u64 t; cvta.to.shared.u64 t, %1; cvt.u32.u64 %0, t; }" : "=r"(a) : "l"(p));
    return a;
}
__device__ __forceinline__ void cp16(uint32_t s, const void* g, bool pred) {
    asm volatile("cp.async.cg.shared.global [%0], [%1], 16, %2;"
                 :: "r"(s), "l"(g), "r"(pred ? 16 : 0));
}
#define CP_COMMIT() asm volatile("cp.async.commit_group;" ::: "memory")
#define CP_WAIT0()  asm volatile("cp.async.wait_group 0;" ::: "memory")
#define CP_WAIT1()  asm volatile("cp.async.wait_group 1;" ::: "memory")

__device__ __forceinline__ void ldsm4(uint32_t& r0, uint32_t& r1, uint32_t& r2, uint32_t& r3,
                                      uint32_t addr) {
    asm volatile("ldmatrix.sync.aligned.m8n8.x4.shared.b16 {%0,%1,%2,%3}, [%4];"
                 : "=r"(r0), "=r"(r1), "=r"(r2), "=r"(r3) : "r"(addr));
}
__device__ __forceinline__ void mma_bf16(float* d, const uint32_t* a, const uint32_t* b) {
    asm volatile(
        "mma.sync.aligned.m16n8k16.row.col.f32.bf16.bf16.f32 "
        "{%0,%1,%2,%3}, {%4,%5,%6,%7}, {%8,%9}, {%0,%1,%2,%3};"
        : "+f"(d[0]), "+f"(d[1]), "+f"(d[2]), "+f"(d[3])
        : "r"(a[0]), "r"(a[1]), "r"(a[2]), "r"(a[3]), "r"(b[0]), "r"(b[1]));
}
__device__ __forceinline__ unsigned pack2bf(float a, float b) {
    __nv_bfloat162 t = make_bfloat162(__float2bfloat16_rn(a), __float2bfloat16_rn(b));
    return *reinterpret_cast<unsigned*>(&t);
}
__device__ __forceinline__ float bfres(float v) {
    return v - __bfloat162float(__float2bfloat16_rn(v));
}

// ---------------------------------------------------------------------------
// CSR build kernels (unchanged; known good)
// ---------------------------------------------------------------------------
__global__ void zero_kernel(int* __restrict__ p, int n) {
    int i = blockIdx.x * blockDim.x + threadIdx.x;
    if (i < n) p[i] = 0;
}
__global__ void count_kernel(const int* __restrict__ dst, int* __restrict__ cnt, int E) {
    int e = blockIdx.x * blockDim.x + threadIdx.x;
    if (e < E) atomicAdd(&cnt[__ldg(&dst[e])], 1);
}
__global__ void scan_block_kernel(const int* __restrict__ in, int* __restrict__ outx,
                                  int* __restrict__ sums, int n) {
    __shared__ int s[2][1024];
    int tid = threadIdx.x;
    int i = blockIdx.x * 1024 + tid;
    int v = (i < n) ? in[i] : 0;
    int pin = 0;
    s[0][tid] = v;
    __syncthreads();
#pragma unroll
    for (int off = 1; off < 1024; off <<= 1) {
        int t = s[pin][tid] + ((tid >= off) ? s[pin][tid - off] : 0);
        s[pin ^ 1][tid] = t;
        pin ^= 1;
        __syncthreads();
    }
    if (i < n) outx[i] = s[pin][tid] - v;
    if (sums != nullptr && tid == 1023) sums[blockIdx.x] = s[pin][1023];
}
__global__ void add_offsets_kernel(const int* __restrict__ pre, const int* __restrict__ top,
                                   int* __restrict__ rowptr, int* __restrict__ cursor, int n) {
    int i = blockIdx.x * blockDim.x + threadIdx.x;
    if (i < n) {
        int v = pre[i] + __ldg(&top[i >> 10]);
        rowptr[i] = v;
        cursor[i] = v;
    }
    if (i == 0) rowptr[n] = NE;
}
__global__ void scatter_kernel(const int* __restrict__ src, const int* __restrict__ dst,
                               const float* __restrict__ w, int* __restrict__ cursor,
                               int2* __restrict__ csr, int E) {
    int e = blockIdx.x * blockDim.x + threadIdx.x;
    if (e >= E) return;
    int d = __ldg(&dst[e]);
    int pos = atomicAdd(&cursor[d], 1);
    csr[pos] = make_int2(__ldg(&src[e]), __float_as_int(__ldg(&w[e])));
}

// ---------------------------------------------------------------------------
// fp32 -> (hi, lo) bf16 plane splits
// ---------------------------------------------------------------------------
__global__ void split_kernel(const float* __restrict__ in, __nv_bfloat16* __restrict__ hi,
                             __nv_bfloat16* __restrict__ lo, int n4) {
    int i = blockIdx.x * blockDim.x + threadIdx.x;
    if (i >= n4) return;
    float4 v = __ldg((const float4*)in + i);
    uint2 h, l;
    h.x = pack2bf(v.x, v.y);
    h.y = pack2bf(v.z, v.w);
    l.x = pack2bf(bfres(v.x), bfres(v.y));
    l.y = pack2bf(bfres(v.z), bfres(v.w));
    ((uint2*)hi)[i] = h;
    ((uint2*)lo)[i] = l;
}
// W[K,N] row-major -> planes [N,K] k-major
__global__ void wsplit_kernel(const float* __restrict__ W, __nv_bfloat16* __restrict__ hi,
                              __nv_bfloat16* __restrict__ lo, int K, int N) {
    int i = blockIdx.x * blockDim.x + threadIdx.x;
    if (i >= K * N) return;
    int n = i / K, k = i % K;
    float v = __ldg(&W[(size_t)k * N + n]);
    hi[(size_t)n * K + k] = __float2bfloat16_rn(v);
    lo[(size_t)n * K + k] = __float2bfloat16_rn(bfres(v));
}

// ---------------------------------------------------------------------------
// HMMA bf16-split GEMM: C[M,N_OUT] = (Ahi+Alo)[M,K] @ (Bhi+Blo)[N_OUT,K]^T
// BM=128, BK=32, cp.async double-buffered. 8 warps (2 m x 4 n), warp tile
// 64 x (N_OUT/4). Rows padded to 80B (5 x 16B) -> ldmatrix conflict-free.
// ---------------------------------------------------------------------------
template <int N_OUT, int K_TOTAL>
__global__ __launch_bounds__(256, 2)
void gemm_mma_kernel(const __nv_bfloat16* __restrict__ Ahi, const __nv_bfloat16* __restrict__ Alo,
                     const __nv_bfloat16* __restrict__ Bhi, const __nv_bfloat16* __restrict__ Blo,
                     float* __restrict__ C, int M) {
    constexpr int NCH = K_TOTAL / 32;          // k-chunks of 32
    constexpr int ROWB = 80;                   // padded row bytes (32 bf16 = 64B + 16B pad)
    constexpr int AT = 128 * ROWB;             // A plane tile bytes
    constexpr int BT = N_OUT * ROWB;           // B plane tile bytes
    constexpr int STAGE = 2 * AT + 2 * BT;
    constexpr int WN = N_OUT / 4;              // warp n-span (32 or 16)
    constexpr int NF = WN / 8;                 // n-frags per warp (4 or 2)

    extern __shared__ char smem[];
    const uint32_t sb = smem_u32(smem);
    const int tid = threadIdx.x;
    const int wid = tid >> 5, lane = tid & 31;
    const int wm = wid & 1, wn = wid >> 1;
    const int bm = blockIdx.x * 128;

    const int lrow = lane & 7;
    const int lmat = lane >> 3;

    float acc[4][NF][4];
#pragma unroll
    for (int mf = 0; mf < 4; mf++)
#pragma unroll
        for (int nf = 0; nf < NF; nf++)
#pragma unroll
            for (int j = 0; j < 4; j++) acc[mf][nf][j] = 0.f;

    auto load_chunk = [&](int ch, int st) {
        const uint32_t base = sb + st * STAGE;
        // A planes: 512 segs each (128 rows x 4 segs)
#pragma unroll
        for (int i = 0; i < 2; i++) {
            int idx = tid + i * 256;
            int row = idx >> 2, seg = idx & 3;
            bool p = (bm + row) < M;
            size_t g = (size_t)(bm + row) * K_TOTAL + ch * 32 + seg * 8;
            cp16(base + row * ROWB + seg * 16, Ahi + g, p);
            cp16(base + AT + row * ROWB + seg * 16, Alo + g, p);
        }
        // B planes: N_OUT*4 segs each
#pragma unroll
        for (int i = 0; i < (N_OUT * 4) / 256; i++) {
            int idx = tid + i * 256;
            int row = idx >> 2, seg = idx & 3;
            size_t g = (size_t)row * K_TOTAL + ch * 32 + seg * 8;
            cp16(base + 2 * AT + row * ROWB + seg * 16, Bhi + g, true);
            cp16(base + 2 * AT + BT + row * ROWB + seg * 16, Blo + g, true);
        }
        CP_COMMIT();
    };

    auto compute = [&](int st) {
        const uint32_t base = sb + st * STAGE;
        const uint32_t aHi = base, aLo = base + AT;
        const uint32_t bHi = base + 2 * AT, bLo = base + 2 * AT + BT;
#pragma unroll
        for (int ks = 0; ks < 2; ks++) {
            const int seg = 2 * ks + (lmat >> 1);
            uint32_t bh[NF][2], bl[NF][2];
#pragma unroll
            for (int p = 0; p < NF / 2; p++) {
                int nrow = wn * WN + p * 16 + lrow + (lmat & 1) * 8;
                uint32_t off = nrow * ROWB + seg * 16;
                uint32_t r0, r1, r2, r3;
                ldsm4(r0, r1, r2, r3, bHi + off);
                bh[2 * p][0] = r0; bh[2 * p + 1][0] = r1;
                bh[2 * p][1] = r2; bh[2 * p + 1][1] = r3;
                ldsm4(r0, r1, r2, r3, bLo + off);
                bl[2 * p][0] = r0; bl[2 * p + 1][0] = r1;
                bl[2 * p][1] = r2; bl[2 * p + 1][1] = r3;
            }
#pragma unroll
            for (int mf = 0; mf < 4; mf++) {
                int arow = wm * 64 + mf * 16 + lrow + (lmat & 1) * 8;
                uint32_t off = arow * ROWB + seg * 16;
                uint32_t ah[4], al[4];
                ldsm4(ah[0], ah[1], ah[2], ah[3], aHi + off);
                ldsm4(al[0], al[1], al[2], al[3], aLo + off);
#pragma unroll
                for (int nf = 0; nf < NF; nf++) {
                    mma_bf16(acc[mf][nf], ah, bh[nf]);
                    mma_bf16(acc[mf][nf], ah, bl[nf]);
                    mma_bf16(acc[mf][nf], al, bh[nf]);
                }
            }
        }
    };

    load_chunk(0, 0);
    for (int c = 0; c < NCH; c++) {
        if (c + 1 < NCH) {
            load_chunk(c + 1, (c + 1) & 1);
            CP_WAIT1();
        } else {
            CP_WAIT0();
        }
        __syncthreads();
        compute(c & 1);
        __syncthreads();
    }

    // epilogue: acc -> C (fp32)
    const int r0 = lane >> 2;
    const int c0 = (lane & 3) * 2;
#pragma unroll
    for (int mf = 0; mf < 4; mf++) {
        int row = bm + wm * 64 + mf * 16 + r0;
#pragma unroll
        for (int half = 0; half < 2; half++) {
            int rr = row + half * 8;
            if (rr < M) {
#pragma unroll
                for (int nf = 0; nf < NF; nf++) {
                    float2 v = make_float2(acc[mf][nf][half * 2], acc[mf][nf][half * 2 + 1]);
                    *(float2*)&C[(size_t)rr * N_OUT + wn * WN + nf * 8 + c0] = v;
                }
            }
        }
    }
}

// ---------------------------------------------------------------------------
// CSR pull-mode SpMM with fused bias (+relu) (+hi/lo split for next GEMM).
// ---------------------------------------------------------------------------
template <int D, bool RELU, bool SPLIT_OUT>
__global__ void spmm_csr_kernel(const float* __restrict__ S, const int2* __restrict__ csr,
                                const int* __restrict__ rowptr, const float* __restrict__ bias,
                                float* __restrict__ outf, __nv_bfloat16* __restrict__ outh,
                                __nv_bfloat16* __restrict__ outl) {
    int warp = (blockIdx.x * blockDim.x + threadIdx.x) >> 5;
    int lane = threadIdx.x & 31;
    if (warp >= NN) return;
    int start = __ldg(&rowptr[warp]);
    int end = __ldg(&rowptr[warp + 1]);

    if (D == 128) {
        float4 acc = __ldg((const float4*)bias + lane);
        for (int e = start; e < end; e++) {
            int2 rec = __ldg(&csr[e]);
            float wt = __int_as_float(rec.y);
            float4 v = __ldg((const float4*)(S + (size_t)rec.x * 128) + lane);
            acc.x = fmaf(wt, v.x, acc.x);
            acc.y = fmaf(wt, v.y, acc.y);
            acc.z = fmaf(wt, v.z, acc.z);
            acc.w = fmaf(wt, v.w, acc.w);
        }
        if (RELU) {
            acc.x = fmaxf(acc.x, 0.f); acc.y = fmaxf(acc.y, 0.f);
            acc.z = fmaxf(acc.z, 0.f); acc.w = fmaxf(acc.w, 0.f);
        }
        if (SPLIT_OUT) {
            uint2 h, l;
            h.x = pack2bf(acc.x, acc.y);  h.y = pack2bf(acc.z, acc.w);
            l.x = pack2bf(bfres(acc.x), bfres(acc.y));
            l.y = pack2bf(bfres(acc.z), bfres(acc.w));
            ((uint2*)(outh + (size_t)warp * 128))[lane] = h;
            ((uint2*)(outl + (size_t)warp * 128))[lane] = l;
        } else {
            *((float4*)(outf + (size_t)warp * 128) + lane) = acc;
        }
    } else {
        float2 acc = __ldg((const float2*)bias + lane);
        for (int e = start; e < end; e++) {
            int2 rec = __ldg(&csr[e]);
            float wt = __int_as_float(rec.y);
            float2 v = __ldg((const float2*)(S + (size_t)rec.x * 64) + lane);
            acc.x = fmaf(wt, v.x, acc.x);
            acc.y = fmaf(wt, v.y, acc.y);
        }
        if (RELU) {
            acc.x = fmaxf(acc.x, 0.f);
            acc.y = fmaxf(acc.y, 0.f);
        }
        if (SPLIT_OUT) {
            ((unsigned*)(outh + (size_t)warp * 64))[lane] = pack2bf(acc.x, acc.y);
            ((unsigned*)(outl + (size_t)warp * 64))[lane] = pack2bf(bfres(acc.x), bfres(acc.y));
        } else {
            *((float2*)(outf + (size_t)warp * 64) + lane) = acc;
        }
    }
}

// ---------------------------------------------------------------------------
extern "C" void kernel_launch(void* const* d_in, const int* in_sizes, int n_in,
                              void* d_out, int out_size) {
    const float* x    = (const float*)d_in[0];
    const int*   esrc = (const int*)d_in[1];
    const int*   edst = (const int*)d_in[2];
    const float* ew   = (const float*)d_in[3];
    const float* W1   = (const float*)d_in[4];
    const float* b1   = (const float*)d_in[5];
    const float* W2   = (const float*)d_in[6];
    const float* b2   = (const float*)d_in[7];
    const float* W3   = (const float*)d_in[8];
    const float* b3   = (const float*)d_in[9];
    float* out = (float*)d_out;

    float* S;
    __nv_bfloat16 *H, *L, *WH, *WL;
    int *cnt, *pre, *bsum, *btop, *rowptr, *cursor;
    int2* csr;
    cudaGetSymbolAddress((void**)&S, g_S);
    cudaGetSymbolAddress((void**)&H, g_H);
    cudaGetSymbolAddress((void**)&L, g_L);
    cudaGetSymbolAddress((void**)&WH, g_WH);
    cudaGetSymbolAddress((void**)&WL, g_WL);
    cudaGetSymbolAddress((void**)&cnt, g_cnt);
    cudaGetSymbolAddress((void**)&pre, g_pre);
    cudaGetSymbolAddress((void**)&bsum, g_bsum);
    cudaGetSymbolAddress((void**)&btop, g_btop);
    cudaGetSymbolAddress((void**)&rowptr, g_rowptr);
    cudaGetSymbolAddress((void**)&cursor, g_cursor);
    cudaGetSymbolAddress((void**)&csr, g_csr);

    const int E = NE, M = NN;
    const int gx = (M + 127) / 128;  // 782 M-tiles

    // smem: STAGE*2; ROWB=80: layer1 = 2*(2*10240 + 2*10240) = 81920
    //                layer2/3 = 2*(2*10240 + 2*5120)  = 61440
    cudaFuncSetAttribute(gemm_mma_kernel<128, 256>, cudaFuncAttributeMaxDynamicSharedMemorySize, 81920);
    cudaFuncSetAttribute(gemm_mma_kernel<64, 128>, cudaFuncAttributeMaxDynamicSharedMemorySize, 61440);
    cudaFuncSetAttribute(gemm_mma_kernel<64, 64>, cudaFuncAttributeMaxDynamicSharedMemorySize, 61440);

    // ----- Build dst-CSR -----
    zero_kernel<<<(NN + 511) / 512, 512>>>(cnt, NN);
    count_kernel<<<(E + 511) / 512, 512>>>(edst, cnt, E);
    scan_block_kernel<<<NBLK_SCAN, 1024>>>(cnt, pre, bsum, NN);
    scan_block_kernel<<<1, 1024>>>(bsum, btop, nullptr, NBLK_SCAN);
    add_offsets_kernel<<<(NN + 511) / 512, 512>>>(pre, btop, rowptr, cursor, NN);
    scatter_kernel<<<(E + 511) / 512, 512>>>(esrc, edst, ew, cursor, csr, E);

    // ----- Operand conversions -----
    split_kernel<<<(NN * 256 / 4 + 255) / 256, 256>>>(x, H, L, NN * 256 / 4);
    wsplit_kernel<<<(256 * 128 + 255) / 256, 256>>>(W1, WH, WL, 256, 128);
    wsplit_kernel<<<(128 * 64 + 255) / 256, 256>>>(W2, WH + 32768, WL + 32768, 128, 64);
    wsplit_kernel<<<(64 * 64 + 255) / 256, 256>>>(W3, WH + 40960, WL + 40960, 64, 64);

    // ----- Layer 1: S = x @ W1; (H,L) = split(relu(adj@S + b1)) -----
    gemm_mma_kernel<128, 256><<<gx, 256, 81920>>>(H, L, WH, WL, S, M);
    spmm_csr_kernel<128, true, true><<<(NN + 7) / 8, 256>>>(S, csr, rowptr, b1, nullptr, H, L);

    // ----- Layer 2: S = A @ W2; (H,L) = split(relu(adj@S + b2)) -----
    gemm_mma_kernel<64, 128><<<gx, 256, 61440>>>(H, L, WH + 32768, WL + 32768, S, M);
    spmm_csr_kernel<64, true, true><<<(NN + 7) / 8, 256>>>(S, csr, rowptr, b2, nullptr, H, L);

    // ----- Layer 3: S = A @ W3; out = adj@S + b3 -----
    gemm_mma_kernel<64, 64><<<gx, 256, 61440>>>(H, L, WH + 40960, WL + 40960, S, M);
    spmm_csr_kernel<64, false, false><<<(NN + 7) / 8, 256>>>(S, csr, rowptr, b3, out, nullptr, nullptr);
}

// round 6
// speedup vs baseline: 2.3674x; 1.1856x over previous
#include <cuda_runtime.h>
#include <cuda_bf16.h>
#include <cstdint>

#define NN 100000
#define NE 1600000
#define NBLK_SCAN 98   // ceil(100000/1024)

// ---------------------------------------------------------------------------
// Scratch (static device arrays; allocation-free per harness rules).
// ---------------------------------------------------------------------------
__device__ float         g_S[(size_t)NN * 128];   // "support" = h @ W (fp32)
__device__ __nv_bfloat16 g_H[(size_t)NN * 128];   // hi-plane of next GEMM A operand
__device__ __nv_bfloat16 g_L[(size_t)NN * 128];   // lo-plane of next GEMM A operand
__device__ __nv_bfloat16 g_WH[45056];             // weight hi planes (W1T|W2T|W3T)
__device__ __nv_bfloat16 g_WL[45056];             // weight lo planes
__device__ int   g_cnt[NN];
__device__ int   g_pre[NN];
__device__ int   g_bsum[1024];
__device__ int   g_btop[1024];
__device__ int   g_rowptr[NN + 1];
__device__ int   g_cursor[NN];
__device__ int2  g_csr[NE];

// ---------------------------------------------------------------------------
// Helpers
// ---------------------------------------------------------------------------
__device__ __forceinline__ uint32_t smem_u32(const void* p) {
    uint32_t a;
    asm("{ .reg .u64 t; cvta.to.shared.u64 t, %1; cvt.u32.u64 %0, t; }" : "=r"(a) : "l"(p));
    return a;
}
__device__ __forceinline__ void cp16(uint32_t s, const void* g, bool pred) {
    asm volatile("cp.async.cg.shared.global [%0], [%1], 16, %2;"
                 :: "r"(s), "l"(g), "r"(pred ? 16 : 0));
}
#define CP_COMMIT() asm volatile("cp.async.commit_group;" ::: "memory")
#define CP_WAIT0()  asm volatile("cp.async.wait_group 0;" ::: "memory")
#define CP_WAIT1()  asm volatile("cp.async.wait_group 1;" ::: "memory")

__device__ __forceinline__ void ldsm4(uint32_t& r0, uint32_t& r1, uint32_t& r2, uint32_t& r3,
                                      uint32_t addr) {
    asm volatile("ldmatrix.sync.aligned.m8n8.x4.shared.b16 {%0,%1,%2,%3}, [%4];"
                 : "=r"(r0), "=r"(r1), "=r"(r2), "=r"(r3) : "r"(addr));
}
__device__ __forceinline__ void mma_bf16(float* d, const uint32_t* a, const uint32_t* b) {
    asm volatile(
        "mma.sync.aligned.m16n8k16.row.col.f32.bf16.bf16.f32 "
        "{%0,%1,%2,%3}, {%4,%5,%6,%7}, {%8,%9}, {%0,%1,%2,%3};"
        : "+f"(d[0]), "+f"(d[1]), "+f"(d[2]), "+f"(d[3])
        : "r"(a[0]), "r"(a[1]), "r"(a[2]), "r"(a[3]), "r"(b[0]), "r"(b[1]));
}
__device__ __forceinline__ unsigned pack2bf(float a, float b) {
    __nv_bfloat162 t = make_bfloat162(__float2bfloat16_rn(a), __float2bfloat16_rn(b));
    return *reinterpret_cast<unsigned*>(&t);
}
__device__ __forceinline__ float bfres(float v) {
    return v - __bfloat162float(__float2bfloat16_rn(v));
}

// ---------------------------------------------------------------------------
// CSR build kernels (known good)
// ---------------------------------------------------------------------------
__global__ void zero_kernel(int* __restrict__ p, int n) {
    int i = blockIdx.x * blockDim.x + threadIdx.x;
    if (i < n) p[i] = 0;
}
__global__ void count_kernel(const int* __restrict__ dst, int* __restrict__ cnt, int E) {
    int e = blockIdx.x * blockDim.x + threadIdx.x;
    if (e < E) atomicAdd(&cnt[__ldg(&dst[e])], 1);
}
__global__ void scan_block_kernel(const int* __restrict__ in, int* __restrict__ outx,
                                  int* __restrict__ sums, int n) {
    __shared__ int s[2][1024];
    int tid = threadIdx.x;
    int i = blockIdx.x * 1024 + tid;
    int v = (i < n) ? in[i] : 0;
    int pin = 0;
    s[0][tid] = v;
    __syncthreads();
#pragma unroll
    for (int off = 1; off < 1024; off <<= 1) {
        int t = s[pin][tid] + ((tid >= off) ? s[pin][tid - off] : 0);
        s[pin ^ 1][tid] = t;
        pin ^= 1;
        __syncthreads();
    }
    if (i < n) outx[i] = s[pin][tid] - v;
    if (sums != nullptr && tid == 1023) sums[blockIdx.x] = s[pin][1023];
}
__global__ void add_offsets_kernel(const int* __restrict__ pre, const int* __restrict__ top,
                                   int* __restrict__ rowptr, int* __restrict__ cursor, int n) {
    int i = blockIdx.x * blockDim.x + threadIdx.x;
    if (i < n) {
        int v = pre[i] + __ldg(&top[i >> 10]);
        rowptr[i] = v;
        cursor[i] = v;
    }
    if (i == 0) rowptr[n] = NE;
}
__global__ void scatter_kernel(const int* __restrict__ src, const int* __restrict__ dst,
                               const float* __restrict__ w, int* __restrict__ cursor,
                               int2* __restrict__ csr, int E) {
    int e = blockIdx.x * blockDim.x + threadIdx.x;
    if (e >= E) return;
    int d = __ldg(&dst[e]);
    int pos = atomicAdd(&cursor[d], 1);
    csr[pos] = make_int2(__ldg(&src[e]), __float_as_int(__ldg(&w[e])));
}

// W[K,N] row-major -> planes [N,K] k-major
__global__ void wsplit_kernel(const float* __restrict__ W, __nv_bfloat16* __restrict__ hi,
                              __nv_bfloat16* __restrict__ lo, int K, int N) {
    int i = blockIdx.x * blockDim.x + threadIdx.x;
    if (i >= K * N) return;
    int n = i / K, k = i % K;
    float v = __ldg(&W[(size_t)k * N + n]);
    hi[(size_t)n * K + k] = __float2bfloat16_rn(v);
    lo[(size_t)n * K + k] = __float2bfloat16_rn(bfres(v));
}

// ---------------------------------------------------------------------------
// HMMA bf16-split GEMM: C[M,N_OUT] = A[M,K] @ (Bhi+Blo)[N_OUT,K]^T
// CONV=true : A is fp32; convert to hi/lo planes in-kernel (reg path).
// CONV=false: A given as pre-split bf16 planes (cp.async path).
// BM=128, BK=32, double-buffered. 8 warps (2m x 4n), warp tile 64 x (N_OUT/4).
// Rows padded to 80B -> ldmatrix conflict-free.
// ---------------------------------------------------------------------------
template <int N_OUT, int K_TOTAL, bool CONV>
__global__ __launch_bounds__(256, 2)
void gemm_mma_kernel(const float* __restrict__ Af,
                     const __nv_bfloat16* __restrict__ Ahi, const __nv_bfloat16* __restrict__ Alo,
                     const __nv_bfloat16* __restrict__ Bhi, const __nv_bfloat16* __restrict__ Blo,
                     float* __restrict__ C, int M) {
    constexpr int NCH = K_TOTAL / 32;
    constexpr int ROWB = 80;
    constexpr int AT = 128 * ROWB;
    constexpr int BT = N_OUT * ROWB;
    constexpr int STAGE = 2 * AT + 2 * BT;
    constexpr int WN = N_OUT / 4;
    constexpr int NF = WN / 8;

    extern __shared__ char smem[];
    const uint32_t sb = smem_u32(smem);
    const int tid = threadIdx.x;
    const int wid = tid >> 5, lane = tid & 31;
    const int wm = wid & 1, wn = wid >> 1;
    const int bm = blockIdx.x * 128;
    const int lrow = lane & 7;
    const int lmat = lane >> 3;

    float acc[4][NF][4];
#pragma unroll
    for (int mf = 0; mf < 4; mf++)
#pragma unroll
        for (int nf = 0; nf < NF; nf++)
#pragma unroll
            for (int j = 0; j < 4; j++) acc[mf][nf][j] = 0.f;

    // A loader: CONV path converts fp32 -> (hi,lo) bf16 in registers.
    auto loadA = [&](int ch, int st) {
        const uint32_t base = sb + st * STAGE;
        if (CONV) {
#pragma unroll
            for (int i = 0; i < 4; i++) {   // 128 rows x 8 segs(4 fp32) / 256 thr
                int idx = tid + i * 256;
                int row = idx >> 3, seg = idx & 7;
                float4 v = make_float4(0.f, 0.f, 0.f, 0.f);
                if (bm + row < M)
                    v = __ldg((const float4*)&Af[(size_t)(bm + row) * K_TOTAL + ch * 32 + seg * 4]);
                uint2 h, l;
                h.x = pack2bf(v.x, v.y);  h.y = pack2bf(v.z, v.w);
                l.x = pack2bf(bfres(v.x), bfres(v.y));
                l.y = pack2bf(bfres(v.z), bfres(v.w));
                uint32_t off = row * ROWB + seg * 8;
                *(uint2*)(smem + st * STAGE + off) = h;
                *(uint2*)(smem + st * STAGE + AT + off) = l;
            }
        } else {
#pragma unroll
            for (int i = 0; i < 2; i++) {   // 128 rows x 4 segs(16B) / 256 thr
                int idx = tid + i * 256;
                int row = idx >> 2, seg = idx & 3;
                bool p = (bm + row) < M;
                size_t g = (size_t)(bm + row) * K_TOTAL + ch * 32 + seg * 8;
                cp16(base + row * ROWB + seg * 16, Ahi + g, p);
                cp16(base + AT + row * ROWB + seg * 16, Alo + g, p);
            }
        }
    };
    auto loadB = [&](int ch, int st) {
        const uint32_t base = sb + st * STAGE;
#pragma unroll
        for (int i = 0; i < (N_OUT * 4) / 256; i++) {
            int idx = tid + i * 256;
            int row = idx >> 2, seg = idx & 3;
            size_t g = (size_t)row * K_TOTAL + ch * 32 + seg * 8;
            cp16(base + 2 * AT + row * ROWB + seg * 16, Bhi + g, true);
            cp16(base + 2 * AT + BT + row * ROWB + seg * 16, Blo + g, true);
        }
        CP_COMMIT();
    };

    auto compute = [&](int st) {
        const uint32_t base = sb + st * STAGE;
        const uint32_t aHi = base, aLo = base + AT;
        const uint32_t bHi = base + 2 * AT, bLo = base + 2 * AT + BT;
#pragma unroll
        for (int ks = 0; ks < 2; ks++) {
            const int seg = 2 * ks + (lmat >> 1);
            uint32_t bh[NF][2], bl[NF][2];
#pragma unroll
            for (int p = 0; p < NF / 2; p++) {
                int nrow = wn * WN + p * 16 + lrow + (lmat & 1) * 8;
                uint32_t off = nrow * ROWB + seg * 16;
                uint32_t r0, r1, r2, r3;
                ldsm4(r0, r1, r2, r3, bHi + off);
                bh[2 * p][0] = r0; bh[2 * p + 1][0] = r1;
                bh[2 * p][1] = r2; bh[2 * p + 1][1] = r3;
                ldsm4(r0, r1, r2, r3, bLo + off);
                bl[2 * p][0] = r0; bl[2 * p + 1][0] = r1;
                bl[2 * p][1] = r2; bl[2 * p + 1][1] = r3;
            }
#pragma unroll
            for (int mf = 0; mf < 4; mf++) {
                int arow = wm * 64 + mf * 16 + lrow + (lmat & 1) * 8;
                uint32_t off = arow * ROWB + seg * 16;
                uint32_t ah[4], al[4];
                ldsm4(ah[0], ah[1], ah[2], ah[3], aHi + off);
                ldsm4(al[0], al[1], al[2], al[3], aLo + off);
#pragma unroll
                for (int nf = 0; nf < NF; nf++) {
                    mma_bf16(acc[mf][nf], ah, bh[nf]);
                    mma_bf16(acc[mf][nf], ah, bl[nf]);
                    mma_bf16(acc[mf][nf], al, bh[nf]);
                }
            }
        }
    };

    loadA(0, 0);
    loadB(0, 0);
    for (int c = 0; c < NCH; c++) {
        if (c + 1 < NCH) {
            loadA(c + 1, (c + 1) & 1);   // CONV: sync STS into free buffer
            loadB(c + 1, (c + 1) & 1);
            CP_WAIT1();
        } else {
            CP_WAIT0();
        }
        __syncthreads();
        compute(c & 1);
        __syncthreads();
    }

    // epilogue: acc -> C (fp32)
    const int r0 = lane >> 2;
    const int c0 = (lane & 3) * 2;
#pragma unroll
    for (int mf = 0; mf < 4; mf++) {
        int row = bm + wm * 64 + mf * 16 + r0;
#pragma unroll
        for (int half = 0; half < 2; half++) {
            int rr = row + half * 8;
            if (rr < M) {
#pragma unroll
                for (int nf = 0; nf < NF; nf++) {
                    float2 v = make_float2(acc[mf][nf][half * 2], acc[mf][nf][half * 2 + 1]);
                    *(float2*)&C[(size_t)rr * N_OUT + wn * WN + nf * 8 + c0] = v;
                }
            }
        }
    }
}

// ---------------------------------------------------------------------------
// CSR pull-mode SpMM with fused bias (+relu) (+hi/lo split for next GEMM).
// One warp per destination node; 2-way unrolled edge loop for MLP.
// ---------------------------------------------------------------------------
template <int D, bool RELU, bool SPLIT_OUT>
__global__ void spmm_csr_kernel(const float* __restrict__ S, const int2* __restrict__ csr,
                                const int* __restrict__ rowptr, const float* __restrict__ bias,
                                float* __restrict__ outf, __nv_bfloat16* __restrict__ outh,
                                __nv_bfloat16* __restrict__ outl) {
    int warp = (blockIdx.x * blockDim.x + threadIdx.x) >> 5;
    int lane = threadIdx.x & 31;
    if (warp >= NN) return;
    int start = __ldg(&rowptr[warp]);
    int end = __ldg(&rowptr[warp + 1]);

    if (D == 128) {
        float4 acc = __ldg((const float4*)bias + lane);
        int e = start;
        for (; e + 1 < end; e += 2) {
            int2 r0 = __ldg(&csr[e]);
            int2 r1 = __ldg(&csr[e + 1]);
            float4 v0 = __ldg((const float4*)(S + (size_t)r0.x * 128) + lane);
            float4 v1 = __ldg((const float4*)(S + (size_t)r1.x * 128) + lane);
            float w0 = __int_as_float(r0.y), w1 = __int_as_float(r1.y);
            acc.x = fmaf(w0, v0.x, acc.x); acc.y = fmaf(w0, v0.y, acc.y);
            acc.z = fmaf(w0, v0.z, acc.z); acc.w = fmaf(w0, v0.w, acc.w);
            acc.x = fmaf(w1, v1.x, acc.x); acc.y = fmaf(w1, v1.y, acc.y);
            acc.z = fmaf(w1, v1.z, acc.z); acc.w = fmaf(w1, v1.w, acc.w);
        }
        if (e < end) {
            int2 r0 = __ldg(&csr[e]);
            float4 v0 = __ldg((const float4*)(S + (size_t)r0.x * 128) + lane);
            float w0 = __int_as_float(r0.y);
            acc.x = fmaf(w0, v0.x, acc.x); acc.y = fmaf(w0, v0.y, acc.y);
            acc.z = fmaf(w0, v0.z, acc.z); acc.w = fmaf(w0, v0.w, acc.w);
        }
        if (RELU) {
            acc.x = fmaxf(acc.x, 0.f); acc.y = fmaxf(acc.y, 0.f);
            acc.z = fmaxf(acc.z, 0.f); acc.w = fmaxf(acc.w, 0.f);
        }
        if (SPLIT_OUT) {
            uint2 h, l;
            h.x = pack2bf(acc.x, acc.y);  h.y = pack2bf(acc.z, acc.w);
            l.x = pack2bf(bfres(acc.x), bfres(acc.y));
            l.y = pack2bf(bfres(acc.z), bfres(acc.w));
            ((uint2*)(outh + (size_t)warp * 128))[lane] = h;
            ((uint2*)(outl + (size_t)warp * 128))[lane] = l;
        } else {
            *((float4*)(outf + (size_t)warp * 128) + lane) = acc;
        }
    } else {
        float2 acc = __ldg((const float2*)bias + lane);
        int e = start;
        for (; e + 1 < end; e += 2) {
            int2 r0 = __ldg(&csr[e]);
            int2 r1 = __ldg(&csr[e + 1]);
            float2 v0 = __ldg((const float2*)(S + (size_t)r0.x * 64) + lane);
            float2 v1 = __ldg((const float2*)(S + (size_t)r1.x * 64) + lane);
            float w0 = __int_as_float(r0.y), w1 = __int_as_float(r1.y);
            acc.x = fmaf(w0, v0.x, acc.x); acc.y = fmaf(w0, v0.y, acc.y);
            acc.x = fmaf(w1, v1.x, acc.x); acc.y = fmaf(w1, v1.y, acc.y);
        }
        if (e < end) {
            int2 r0 = __ldg(&csr[e]);
            float2 v0 = __ldg((const float2*)(S + (size_t)r0.x * 64) + lane);
            float w0 = __int_as_float(r0.y);
            acc.x = fmaf(w0, v0.x, acc.x); acc.y = fmaf(w0, v0.y, acc.y);
        }
        if (RELU) {
            acc.x = fmaxf(acc.x, 0.f);
            acc.y = fmaxf(acc.y, 0.f);
        }
        if (SPLIT_OUT) {
            ((unsigned*)(outh + (size_t)warp * 64))[lane] = pack2bf(acc.x, acc.y);
            ((unsigned*)(outl + (size_t)warp * 64))[lane] = pack2bf(bfres(acc.x), bfres(acc.y));
        } else {
            *((float2*)(outf + (size_t)warp * 64) + lane) = acc;
        }
    }
}

// ---------------------------------------------------------------------------
extern "C" void kernel_launch(void* const* d_in, const int* in_sizes, int n_in,
                              void* d_out, int out_size) {
    const float* x    = (const float*)d_in[0];
    const int*   esrc = (const int*)d_in[1];
    const int*   edst = (const int*)d_in[2];
    const float* ew   = (const float*)d_in[3];
    const float* W1   = (const float*)d_in[4];
    const float* b1   = (const float*)d_in[5];
    const float* W2   = (const float*)d_in[6];
    const float* b2   = (const float*)d_in[7];
    const float* W3   = (const float*)d_in[8];
    const float* b3   = (const float*)d_in[9];
    float* out = (float*)d_out;

    float* S;
    __nv_bfloat16 *H, *L, *WH, *WL;
    int *cnt, *pre, *bsum, *btop, *rowptr, *cursor;
    int2* csr;
    cudaGetSymbolAddress((void**)&S, g_S);
    cudaGetSymbolAddress((void**)&H, g_H);
    cudaGetSymbolAddress((void**)&L, g_L);
    cudaGetSymbolAddress((void**)&WH, g_WH);
    cudaGetSymbolAddress((void**)&WL, g_WL);
    cudaGetSymbolAddress((void**)&cnt, g_cnt);
    cudaGetSymbolAddress((void**)&pre, g_pre);
    cudaGetSymbolAddress((void**)&bsum, g_bsum);
    cudaGetSymbolAddress((void**)&btop, g_btop);
    cudaGetSymbolAddress((void**)&rowptr, g_rowptr);
    cudaGetSymbolAddress((void**)&cursor, g_cursor);
    cudaGetSymbolAddress((void**)&csr, g_csr);

    // Side stream + events: created once on the first (uncaptured) call.
    static cudaStream_t s2 = nullptr;
    static cudaEvent_t evFork = nullptr, evJoin = nullptr;
    if (s2 == nullptr) {
        cudaStreamCreateWithFlags(&s2, cudaStreamNonBlocking);
        cudaEventCreateWithFlags(&evFork, cudaEventDisableTiming);
        cudaEventCreateWithFlags(&evJoin, cudaEventDisableTiming);
    }

    const int E = NE, M = NN;
    const int gx = (M + 127) / 128;

    cudaFuncSetAttribute(gemm_mma_kernel<128, 256, true>, cudaFuncAttributeMaxDynamicSharedMemorySize, 81920);
    cudaFuncSetAttribute(gemm_mma_kernel<64, 128, false>, cudaFuncAttributeMaxDynamicSharedMemorySize, 61440);
    cudaFuncSetAttribute(gemm_mma_kernel<64, 64, false>, cudaFuncAttributeMaxDynamicSharedMemorySize, 61440);

    // ----- Fork: CSR build + W2/W3 splits on side stream -----
    cudaEventRecord(evFork, 0);
    cudaStreamWaitEvent(s2, evFork, 0);
    zero_kernel<<<(NN + 511) / 512, 512, 0, s2>>>(cnt, NN);
    count_kernel<<<(E + 511) / 512, 512, 0, s2>>>(edst, cnt, E);
    scan_block_kernel<<<NBLK_SCAN, 1024, 0, s2>>>(cnt, pre, bsum, NN);
    scan_block_kernel<<<1, 1024, 0, s2>>>(bsum, btop, nullptr, NBLK_SCAN);
    add_offsets_kernel<<<(NN + 511) / 512, 512, 0, s2>>>(pre, btop, rowptr, cursor, NN);
    scatter_kernel<<<(E + 511) / 512, 512, 0, s2>>>(esrc, edst, ew, cursor, csr, E);
    wsplit_kernel<<<(128 * 64 + 255) / 256, 256, 0, s2>>>(W2, WH + 32768, WL + 32768, 128, 64);
    wsplit_kernel<<<(64 * 64 + 255) / 256, 256, 0, s2>>>(W3, WH + 40960, WL + 40960, 64, 64);
    cudaEventRecord(evJoin, s2);

    // ----- Main stream: W1 split + GEMM1 (fp32 A, in-kernel convert) -----
    wsplit_kernel<<<(256 * 128 + 255) / 256, 256>>>(W1, WH, WL, 256, 128);
    gemm_mma_kernel<128, 256, true><<<gx, 256, 81920>>>(x, nullptr, nullptr, WH, WL, S, M);

    // ----- Join, then Layer 1 SpMM -----
    cudaStreamWaitEvent(0, evJoin, 0);
    spmm_csr_kernel<128, true, true><<<(NN + 7) / 8, 256>>>(S, csr, rowptr, b1, nullptr, H, L);

    // ----- Layer 2 -----
    gemm_mma_kernel<64, 128, false><<<gx, 256, 61440>>>(nullptr, H, L, WH + 32768, WL + 32768, S, M);
    spmm_csr_kernel<64, true, true><<<(NN + 7) / 8, 256>>>(S, csr, rowptr, b2, nullptr, H, L);

    // ----- Layer 3 -----
    gemm_mma_kernel<64, 64, false><<<gx, 256, 61440>>>(nullptr, H, L, WH + 40960, WL + 40960, S, M);
    spmm_csr_kernel<64, false, false><<<(NN + 7) / 8, 256>>>(S, csr, rowptr, b3, out, nullptr, nullptr);
}